// round 11
// baseline (speedup 1.0000x reference)
#include <cuda_runtime.h>
#include <cstdint>

// ---------------------------------------------------------------------------
// GeneratorNetwork: 512-step 2-layer LSTM (B=4096, H=512) + MDN head.
//   * idea = tanh(latent @ W_unpack^T + b) precomputed once.
//   * base1 = idea @ W_ih1[:, :512]^T + b_ih1 + b_hh1 precomputed once
//     (x = [idea, prev], prev = [angles, 0] -> rank-1 update in epilogue).
//   * ONE persistent kernel runs all 512 steps (software grid barrier) to
//     keep the CUDA graph tiny (5 nodes).
//   * TF32 tensor-core GEMMs with fused LSTM cell epilogues; gate weights
//     pre-interleaved (n' = unit*4 + gate); h1/h2 ping-pong.
//   * R11: fragment loads use LDS.64 via implicit k-slot permutation --
//     mma k-slot pair (i, i+4) reads adjacent smem floats (2i, 2i+1) for
//     BOTH A and B (reduction is permutation-invariant when consistent).
//     96 LDS.32 -> 48 LDS.64 per k-tile. Pitch 40 floats = conflict-free.
// ---------------------------------------------------------------------------

#define BATCH 4096
#define RNN   512
#define CODE  512
#define GATES 2048
#define SEG   512
#define NCTA  148

// ---------------- device state (no cudaMalloc allowed) --------------------
__device__ __align__(256) float g_idea [BATCH * CODE];
__device__ __align__(256) float g_base1[BATCH * GATES];
__device__ __align__(256) float g_h1[2][BATCH * RNN];
__device__ __align__(256) float g_c1   [BATCH * RNN];
__device__ __align__(256) float g_h2[2][BATCH * RNN];
__device__ __align__(256) float g_c2   [BATCH * RNN];
__device__ __align__(256) float g_angles[BATCH];
__device__ __align__(256) float g_Wih1r[GATES * RNN];      // interleaved, tf32-rounded
__device__ __align__(256) float g_Whh1r[GATES * RNN];
__device__ __align__(256) float g_W2r  [GATES * 1024];     // [W_ih2 | W_hh2], K=1024
__device__ __align__(256) float g_wprev1[GATES];           // W_ih1[:,512], interleaved
__device__ __align__(256) float g_bias1[GATES];            // b_ih1+b_hh1, interleaved
__device__ __align__(256) float g_bias2[GATES];            // b_ih2+b_hh2, interleaved
__device__ __align__(256) float g_Whead[15 * RNN];         // [mix(5); mu(5); var(5)]
__device__ __align__(256) float g_bhead[16];
__device__ int g_bar;                                      // global barrier (monotonic)
__device__ int g_ctrs[2 * SEG];                            // per-phase tile counters

// ---------------- helpers --------------------------------------------------
__device__ __forceinline__ float tf32r(float x) {
    uint32_t u;
    asm("cvt.rna.tf32.f32 %0, %1;\n" : "=r"(u) : "f"(x));
    return __uint_as_float(u);
}

__device__ __forceinline__ void cp16(float* dst, const float* src) {
    uint32_t d = (uint32_t)__cvta_generic_to_shared(dst);
    asm volatile("cp.async.cg.shared.global [%0], [%1], 16;\n" :: "r"(d), "l"(src));
}

__device__ __forceinline__ float sigmoid_f(float x) {
    return 1.0f / (1.0f + __expf(-x));
}
__device__ __forceinline__ float tanh_f(float x) {
    x = fminf(fmaxf(x, -15.f), 15.f);
    float e = __expf(2.f * x);
    return (e - 1.f) / (e + 1.f);
}

// software grid barrier (all 148 CTAs co-resident: 1 CTA/SM by smem usage)
__device__ __forceinline__ void gsync(int& epoch) {
    __syncthreads();
    if (threadIdx.x == 0) {
        int target = (++epoch) * (int)gridDim.x;
        __threadfence();
        atomicAdd(&g_bar, 1);
        int v;
        do {
            asm volatile("ld.acquire.gpu.global.s32 %0, [%1];"
                         : "=r"(v) : "l"(&g_bar));
        } while (v < target);
    }
    __syncthreads();
}

// ---------------- init + reorder -------------------------------------------
__global__ void zero_kernel() {
    size_t i = (size_t)blockIdx.x * blockDim.x + threadIdx.x;
    if (i < (size_t)BATCH * RNN) {
        g_h1[0][i] = 0.f; g_h2[0][i] = 0.f;
        g_c1[i]    = 0.f; g_c2[i]    = 0.f;
    }
    if (i < BATCH) g_angles[i] = 0.f;
    if (i < 2 * SEG) g_ctrs[i] = 0;
    if (i == 0) g_bar = 0;
}

__global__ void reorder_kernel(
    const float* __restrict__ W_ih1, const float* __restrict__ W_hh1,
    const float* __restrict__ b_ih1, const float* __restrict__ b_hh1,
    const float* __restrict__ W_ih2, const float* __restrict__ W_hh2,
    const float* __restrict__ b_ih2, const float* __restrict__ b_hh2,
    const float* __restrict__ W_mu,  const float* __restrict__ b_mu,
    const float* __restrict__ W_var, const float* __restrict__ b_var,
    const float* __restrict__ W_mix, const float* __restrict__ b_mix)
{
    int np = blockIdx.x;          // interleaved gate index 0..2047
    int k  = threadIdx.x;         // 0..511
    int gate = np & 3, unit = np >> 2;
    int n = gate * 512 + unit;    // original row in the 4*RNN weight matrices

    g_Wih1r[np * 512 + k]        = tf32r(W_ih1[n * 514 + k]);   // W_ih1 is [2048, 514]
    g_Whh1r[np * 512 + k]        = tf32r(W_hh1[n * 512 + k]);
    g_W2r  [np * 1024 + k]       = tf32r(W_ih2[n * 512 + k]);
    g_W2r  [np * 1024 + 512 + k] = tf32r(W_hh2[n * 512 + k]);

    if (k == 0) {
        g_wprev1[np] = W_ih1[n * 514 + 512];
        g_bias1[np]  = b_ih1[n] + b_hh1[n];
        g_bias2[np]  = b_ih2[n] + b_hh2[n];
    }
    if (np < 15) {
        const float* src = (np < 5) ? (W_mix + np * 512)
                         : (np < 10) ? (W_mu + (np - 5) * 512)
                                     : (W_var + (np - 10) * 512);
        g_Whead[np * 512 + k] = src[k];
        if (k == 0)
            g_bhead[np] = (np < 5) ? b_mix[np] : (np < 10) ? b_mu[np - 5] : b_var[np - 10];
    }
}

// ---------------- TF32 GEMM tile with fused epilogues -----------------------
// C[4096, N] = A[4096, K] @ Bw[N, K]^T (NT, both K-contiguous)
// modes: 0=idea(tanh), 1=base1(+bias), 2=LSTM1 fused, 3=LSTM2 fused (K=1024)
#define BM 128
#define BN 128
#define BK 32
#define STG 3
#define ASTR 40
#define STAGE_FLOATS (2 * 128 * ASTR)   // floats per stage (A+B)

__device__ void gemm_tile(int mode, int pp,
                          const float* __restrict__ xA,
                          const float* __restrict__ xB,
                          const float* __restrict__ xbias,
                          int m0, int n0, float* smem)
{
    const int tid  = threadIdx.x;
    const int lane = tid & 31;
    const int warp = tid >> 5;
    const int wm   = warp & 3;     // 4 warps along M (32 rows each)
    const int wn   = warp >> 2;    // 2 warps along N (64 cols each)

    const float* A0; const float* A1 = nullptr; const float* Bw;
    int K;
    if      (mode == 0) { A0 = xA;           Bw = xB;       K = 512;  }
    else if (mode == 1) { A0 = g_idea;       Bw = g_Wih1r;  K = 512;  }
    else if (mode == 2) { A0 = g_h1[pp];     Bw = g_Whh1r;  K = 512;  }
    else                { A0 = g_h1[pp ^ 1]; A1 = g_h2[pp]; Bw = g_W2r; K = 1024; }
    const int KT = K / BK;

    float acc[2][8][4];
    #pragma unroll
    for (int a = 0; a < 2; ++a)
        #pragma unroll
        for (int b = 0; b < 8; ++b)
            #pragma unroll
            for (int c = 0; c < 4; ++c) acc[a][b][c] = 0.f;

    auto load_tile = [&](int buf, int kt) {
        const int k0 = kt * BK;
        const float* Asrc = A0; int kk = k0;
        if (A1 != nullptr && k0 >= 512) { Asrc = A1; kk = k0 - 512; }
        float* as = smem + buf * STAGE_FLOATS;
        float* bs = as + 128 * ASTR;
        #pragma unroll
        for (int i = 0; i < 4; ++i) {
            int cid = tid + 256 * i;
            int row = cid >> 3;
            int c4  = (cid & 7) << 2;
            cp16(&as[row * ASTR + c4], &Asrc[(size_t)(m0 + row) * 512 + kk + c4]);
        }
        #pragma unroll
        for (int i = 0; i < 4; ++i) {
            int cid = tid + 256 * i;
            int row = cid >> 3;
            int c4  = (cid & 7) << 2;
            cp16(&bs[row * ASTR + c4], &Bw[(size_t)(n0 + row) * K + k0 + c4]);
        }
    };

    // mma k-slot pairing trick: slot pair (i, i+4) of BOTH A and B fragments
    // is fed from adjacent smem floats (2i, 2i+1). The k-reduction is
    // invariant under any consistent slot permutation -> one LDS.64 per pair.
    auto compute = [&](int buf) {
        const float* as = smem + buf * STAGE_FLOATS;
        const float* bs = as + 128 * ASTR;
        #pragma unroll
        for (int ks = 0; ks < 4; ++ks) {
            const int kp = ks * 8 + ((lane & 3) << 1);
            uint32_t af[2][4];
            #pragma unroll
            for (int tm = 0; tm < 2; ++tm) {
                int r = wm * 32 + tm * 16 + (lane >> 2);
                float2 lo = *(const float2*)&as[r * ASTR + kp];
                float2 hi = *(const float2*)&as[(r + 8) * ASTR + kp];
                af[tm][0] = __float_as_uint(lo.x);
                af[tm][2] = __float_as_uint(lo.y);
                af[tm][1] = __float_as_uint(hi.x);
                af[tm][3] = __float_as_uint(hi.y);
            }
            uint32_t bf[8][2];
            #pragma unroll
            for (int tn = 0; tn < 8; ++tn) {
                int r = wn * 64 + tn * 8 + (lane >> 2);
                float2 bv = *(const float2*)&bs[r * ASTR + kp];
                bf[tn][0] = __float_as_uint(bv.x);
                bf[tn][1] = __float_as_uint(bv.y);
            }
            #pragma unroll
            for (int tm = 0; tm < 2; ++tm)
                #pragma unroll
                for (int tn = 0; tn < 8; ++tn)
                    asm volatile(
                        "mma.sync.aligned.m16n8k8.row.col.f32.tf32.tf32.f32 "
                        "{%0,%1,%2,%3},{%4,%5,%6,%7},{%8,%9},{%0,%1,%2,%3};\n"
                        : "+f"(acc[tm][tn][0]), "+f"(acc[tm][tn][1]),
                          "+f"(acc[tm][tn][2]), "+f"(acc[tm][tn][3])
                        : "r"(af[tm][0]), "r"(af[tm][1]), "r"(af[tm][2]), "r"(af[tm][3]),
                          "r"(bf[tn][0]), "r"(bf[tn][1]));
        }
    };

    // 3-stage cp.async pipeline
    #pragma unroll
    for (int s = 0; s < STG - 1; ++s) {
        load_tile(s, s);
        asm volatile("cp.async.commit_group;\n");
    }
    asm volatile("cp.async.wait_group %0;\n" :: "n"(STG - 2));
    __syncthreads();

    for (int kt = 0; kt < KT; ++kt) {
        int nk = kt + STG - 1;
        if (nk < KT) load_tile(nk % STG, nk);
        asm volatile("cp.async.commit_group;\n");
        compute(kt % STG);
        asm volatile("cp.async.wait_group %0;\n" :: "n"(STG - 2));
        __syncthreads();
    }
    asm volatile("cp.async.wait_group 0;\n");

    // ---- epilogue: park accumulators in smem, then fused math -------------
    float* gs = smem;   // 128 x 132 f32 tile reusing pipeline smem
    #pragma unroll
    for (int tm = 0; tm < 2; ++tm) {
        #pragma unroll
        for (int tn = 0; tn < 8; ++tn) {
            int r = wm * 32 + tm * 16 + (lane >> 2);
            int c = wn * 64 + tn * 8 + ((lane & 3) << 1);
            gs[r * 132 + c]           = acc[tm][tn][0];
            gs[r * 132 + c + 1]       = acc[tm][tn][1];
            gs[(r + 8) * 132 + c]     = acc[tm][tn][2];
            gs[(r + 8) * 132 + c + 1] = acc[tm][tn][3];
        }
    }
    __syncthreads();

    #pragma unroll 4
    for (int i = 0; i < 16; ++i) {
        int t   = i * 256 + tid;
        int row = t >> 5, q = t & 31;
        int b   = m0 + row;
        int np  = n0 + (q << 2);
        float4 v = *(float4*)&gs[row * 132 + (q << 2)];

        if (mode == 0) {
            float4 bb = *(const float4*)&xbias[np];
            float4 o;
            o.x = tf32r(tanh_f(v.x + bb.x));
            o.y = tf32r(tanh_f(v.y + bb.y));
            o.z = tf32r(tanh_f(v.z + bb.z));
            o.w = tf32r(tanh_f(v.w + bb.w));
            *(float4*)&g_idea[(size_t)b * 512 + np] = o;
        } else if (mode == 1) {
            float4 bb = *(const float4*)&g_bias1[np];
            v.x += bb.x; v.y += bb.y; v.z += bb.z; v.w += bb.w;
            *(float4*)&g_base1[(size_t)b * 2048 + np] = v;
        } else {
            float gi, gf, gg, go;
            float* cbuf; float* hout;
            if (mode == 2) {
                float4 bb = *(const float4*)&g_base1[(size_t)b * 2048 + np];
                float4 wp = *(const float4*)&g_wprev1[np];
                float ang = g_angles[b];
                gi = v.x + bb.x + ang * wp.x;
                gf = v.y + bb.y + ang * wp.y;
                gg = v.z + bb.z + ang * wp.z;
                go = v.w + bb.w + ang * wp.w;
                cbuf = g_c1; hout = g_h1[pp ^ 1];
            } else {
                float4 bb = *(const float4*)&g_bias2[np];
                gi = v.x + bb.x; gf = v.y + bb.y;
                gg = v.z + bb.z; go = v.w + bb.w;
                cbuf = g_c2; hout = g_h2[pp ^ 1];
            }
            int u = np >> 2;                       // global unit index
            size_t ci = (size_t)b * 512 + u;
            float cold = cbuf[ci];
            float si = sigmoid_f(gi);
            float sf = sigmoid_f(gf);
            float so = sigmoid_f(go);
            float cn = sf * cold + si * tanh_f(gg);
            cbuf[ci] = cn;
            hout[ci] = tf32r(so * tanh_f(cn));
        }
    }
    __syncthreads();
}

__global__ void __launch_bounds__(256, 1)
gemm_kernel(int mode, int pp,
            const float* __restrict__ xA,
            const float* __restrict__ xB,
            const float* __restrict__ xbias)
{
    extern __shared__ float smem[];
    gemm_tile(mode, pp, xA, xB, xbias, blockIdx.y * BM, blockIdx.x * BN, smem);
}

// ---------------- MDN head: one warp per batch row --------------------------
__device__ __forceinline__ void head_row(const float* __restrict__ eps,
                                         float* __restrict__ out,
                                         int s, int hp, int gw, int lane)
{
    const float* h = &g_h2[hp][(size_t)gw * RNN];

    float accv[15];
    #pragma unroll
    for (int j = 0; j < 15; ++j) accv[j] = 0.f;
    #pragma unroll
    for (int i = 0; i < 16; ++i) {
        float hv = h[lane + 32 * i];
        #pragma unroll
        for (int j = 0; j < 15; ++j)
            accv[j] += hv * g_Whead[j * 512 + 32 * i + lane];
    }
    #pragma unroll
    for (int j = 0; j < 15; ++j) {
        #pragma unroll
        for (int off = 16; off; off >>= 1)
            accv[j] += __shfl_xor_sync(0xffffffffu, accv[j], off);
    }
    if (lane == 0) {
        float lmax = -1e30f;
        #pragma unroll
        for (int j = 0; j < 5; ++j) {
            accv[j] += g_bhead[j];
            lmax = fmaxf(lmax, accv[j]);
        }
        float e[5], esum = 0.f;
        #pragma unroll
        for (int j = 0; j < 5; ++j) { e[j] = __expf(accv[j] - lmax); esum += e[j]; }
        float inv = 1.f / esum;
        float mu = 0.f, sg = 0.f;
        #pragma unroll
        for (int j = 0; j < 5; ++j) {
            float rho = e[j] * inv;
            mu += rho * (accv[5 + j] + g_bhead[5 + j]);
            sg += rho * __expf(accv[10 + j] + g_bhead[10 + j]);   // t = 0
        }
        float a = tanh_f(mu + sg * eps[(size_t)s * BATCH + gw]);
        g_angles[gw] = a;
        ((float2*)out)[(size_t)gw * SEG + s] = make_float2(a, 0.f);
    }
}

// ---------------- persistent kernel: all 512 steps ---------------------------
__global__ void __launch_bounds__(256, 1)
persist_kernel(const float* __restrict__ eps, float* __restrict__ out)
{
    extern __shared__ float smem[];
    __shared__ int s_tile;
    int epoch = 0;
    const int lane = threadIdx.x & 31;
    const int wg   = blockIdx.x * 8 + (threadIdx.x >> 5);   // global warp id

    for (int s = 0; s < SEG; ++s) {
        int pp = s & 1;

        // phase A: LSTM1 (dynamic 128x128 tiles, 512 total)
        for (;;) {
            __syncthreads();
            if (threadIdx.x == 0) s_tile = atomicAdd(&g_ctrs[2 * s], 1);
            __syncthreads();
            int t = s_tile;
            if (t >= 512) break;
            gemm_tile(2, pp, nullptr, nullptr, nullptr,
                      (t >> 4) * BM, (t & 15) * BN, smem);
        }
        gsync(epoch);

        // phase B: LSTM2 (K=1024)
        for (;;) {
            __syncthreads();
            if (threadIdx.x == 0) s_tile = atomicAdd(&g_ctrs[2 * s + 1], 1);
            __syncthreads();
            int t = s_tile;
            if (t >= 512) break;
            gemm_tile(3, pp, nullptr, nullptr, nullptr,
                      (t >> 4) * BM, (t & 15) * BN, smem);
        }
        gsync(epoch);

        // phase C: MDN heads (one warp per batch row)
        for (int row = wg; row < BATCH; row += NCTA * 8)
            head_row(eps, out, s, pp ^ 1, row, lane);
        gsync(epoch);
    }
}

// ---------------- launch ----------------------------------------------------
extern "C" void kernel_launch(void* const* d_in, const int* in_sizes, int n_in,
                              void* d_out, int out_size)
{
    const float* latent   = (const float*)d_in[0];
    const float* W_unpack = (const float*)d_in[1];
    const float* b_unpack = (const float*)d_in[2];
    const float* W_ih1    = (const float*)d_in[3];
    const float* W_hh1    = (const float*)d_in[4];
    const float* b_ih1    = (const float*)d_in[5];
    const float* b_hh1    = (const float*)d_in[6];
    const float* W_ih2    = (const float*)d_in[7];
    const float* W_hh2    = (const float*)d_in[8];
    const float* b_ih2    = (const float*)d_in[9];
    const float* b_hh2    = (const float*)d_in[10];
    const float* W_mu     = (const float*)d_in[11];
    const float* b_mu     = (const float*)d_in[12];
    const float* W_var    = (const float*)d_in[13];
    const float* b_var    = (const float*)d_in[14];
    const float* W_mix    = (const float*)d_in[15];
    const float* b_mix    = (const float*)d_in[16];
    const float* eps      = (const float*)d_in[17];
    float* out = (float*)d_out;

    const size_t shmem = (size_t)STG * STAGE_FLOATS * sizeof(float);   // 122880 B
    cudaFuncSetAttribute(gemm_kernel, cudaFuncAttributeMaxDynamicSharedMemorySize,
                         (int)shmem);
    cudaFuncSetAttribute(persist_kernel, cudaFuncAttributeMaxDynamicSharedMemorySize,
                         (int)shmem);

    zero_kernel<<<(BATCH * RNN + 255) / 256, 256>>>();
    reorder_kernel<<<GATES, 512>>>(W_ih1, W_hh1, b_ih1, b_hh1,
                                   W_ih2, W_hh2, b_ih2, b_hh2,
                                   W_mu, b_mu, W_var, b_var, W_mix, b_mix);

    // one-time: idea = tanh(latent @ W_unpack^T + b_unpack)
    gemm_kernel<<<dim3(CODE / BN, BATCH / BM), 256, shmem>>>(0, 0, latent, W_unpack, b_unpack);
    // one-time: base1 = idea @ W_ih1'[:, :512]^T + b_ih1 + b_hh1 (interleaved)
    gemm_kernel<<<dim3(GATES / BN, BATCH / BM), 256, shmem>>>(1, 0, nullptr, nullptr, nullptr);

    // all 512 steps in ONE persistent kernel (5 graph nodes total)
    persist_kernel<<<NCTA, 256, shmem>>>(eps, out);
}

// round 12
// speedup vs baseline: 1.1543x; 1.1543x over previous
#include <cuda_runtime.h>
#include <cstdint>

// ---------------------------------------------------------------------------
// GeneratorNetwork: 512-step 2-layer LSTM (B=4096, H=512) + MDN head.
//   * idea = tanh(latent @ W_unpack^T + b) precomputed once.
//   * base1 = idea @ W_ih1[:, :512]^T + b_ih1 + b_hh1 precomputed once
//     (x = [idea, prev], prev = [angles, 0] -> rank-1 update in epilogue).
//   * ONE persistent kernel runs all 512 steps (software grid barrier).
//   * TF32 tensor-core GEMMs with fused LSTM cell epilogues; gate weights
//     pre-interleaved (n' = unit*4 + gate); h1/h2 ping-pong.
//   * R12: 512 threads / 16 warps per CTA (4x4 warp grid, 32x32 warp-tiles)
//     to hide LDS latency -- R10/R11 profiles showed latency-bound mainloop
//     (2600 cyc/ktile vs 768-cyc crossbar floor) at 8 warps. R11's LDS.64
//     experiment reverted (alu% exploded, net regression).
// ---------------------------------------------------------------------------

#define BATCH 4096
#define RNN   512
#define CODE  512
#define GATES 2048
#define SEG   512
#define NCTA  148
#define NTHR  512

// ---------------- device state (no cudaMalloc allowed) --------------------
__device__ __align__(256) float g_idea [BATCH * CODE];
__device__ __align__(256) float g_base1[BATCH * GATES];
__device__ __align__(256) float g_h1[2][BATCH * RNN];
__device__ __align__(256) float g_c1   [BATCH * RNN];
__device__ __align__(256) float g_h2[2][BATCH * RNN];
__device__ __align__(256) float g_c2   [BATCH * RNN];
__device__ __align__(256) float g_angles[BATCH];
__device__ __align__(256) float g_Wih1r[GATES * RNN];      // interleaved, tf32-rounded
__device__ __align__(256) float g_Whh1r[GATES * RNN];
__device__ __align__(256) float g_W2r  [GATES * 1024];     // [W_ih2 | W_hh2], K=1024
__device__ __align__(256) float g_wprev1[GATES];           // W_ih1[:,512], interleaved
__device__ __align__(256) float g_bias1[GATES];            // b_ih1+b_hh1, interleaved
__device__ __align__(256) float g_bias2[GATES];            // b_ih2+b_hh2, interleaved
__device__ __align__(256) float g_Whead[15 * RNN];         // [mix(5); mu(5); var(5)]
__device__ __align__(256) float g_bhead[16];
__device__ int g_bar;                                      // global barrier (monotonic)
__device__ int g_ctrs[2 * SEG];                            // per-phase tile counters

// ---------------- helpers --------------------------------------------------
__device__ __forceinline__ float tf32r(float x) {
    uint32_t u;
    asm("cvt.rna.tf32.f32 %0, %1;\n" : "=r"(u) : "f"(x));
    return __uint_as_float(u);
}

__device__ __forceinline__ void cp16(float* dst, const float* src) {
    uint32_t d = (uint32_t)__cvta_generic_to_shared(dst);
    asm volatile("cp.async.cg.shared.global [%0], [%1], 16;\n" :: "r"(d), "l"(src));
}

__device__ __forceinline__ float sigmoid_f(float x) {
    return 1.0f / (1.0f + __expf(-x));
}
__device__ __forceinline__ float tanh_f(float x) {
    x = fminf(fmaxf(x, -15.f), 15.f);
    float e = __expf(2.f * x);
    return (e - 1.f) / (e + 1.f);
}

// software grid barrier (all 148 CTAs co-resident: 1 CTA/SM by smem usage)
__device__ __forceinline__ void gsync(int& epoch) {
    __syncthreads();
    if (threadIdx.x == 0) {
        int target = (++epoch) * (int)gridDim.x;
        __threadfence();
        atomicAdd(&g_bar, 1);
        int v;
        do {
            asm volatile("ld.acquire.gpu.global.s32 %0, [%1];"
                         : "=r"(v) : "l"(&g_bar));
        } while (v < target);
    }
    __syncthreads();
}

// ---------------- init + reorder -------------------------------------------
__global__ void zero_kernel() {
    size_t i = (size_t)blockIdx.x * blockDim.x + threadIdx.x;
    if (i < (size_t)BATCH * RNN) {
        g_h1[0][i] = 0.f; g_h2[0][i] = 0.f;
        g_c1[i]    = 0.f; g_c2[i]    = 0.f;
    }
    if (i < BATCH) g_angles[i] = 0.f;
    if (i < 2 * SEG) g_ctrs[i] = 0;
    if (i == 0) g_bar = 0;
}

__global__ void reorder_kernel(
    const float* __restrict__ W_ih1, const float* __restrict__ W_hh1,
    const float* __restrict__ b_ih1, const float* __restrict__ b_hh1,
    const float* __restrict__ W_ih2, const float* __restrict__ W_hh2,
    const float* __restrict__ b_ih2, const float* __restrict__ b_hh2,
    const float* __restrict__ W_mu,  const float* __restrict__ b_mu,
    const float* __restrict__ W_var, const float* __restrict__ b_var,
    const float* __restrict__ W_mix, const float* __restrict__ b_mix)
{
    int np = blockIdx.x;          // interleaved gate index 0..2047
    int k  = threadIdx.x;         // 0..511
    int gate = np & 3, unit = np >> 2;
    int n = gate * 512 + unit;    // original row in the 4*RNN weight matrices

    g_Wih1r[np * 512 + k]        = tf32r(W_ih1[n * 514 + k]);   // W_ih1 is [2048, 514]
    g_Whh1r[np * 512 + k]        = tf32r(W_hh1[n * 512 + k]);
    g_W2r  [np * 1024 + k]       = tf32r(W_ih2[n * 512 + k]);
    g_W2r  [np * 1024 + 512 + k] = tf32r(W_hh2[n * 512 + k]);

    if (k == 0) {
        g_wprev1[np] = W_ih1[n * 514 + 512];
        g_bias1[np]  = b_ih1[n] + b_hh1[n];
        g_bias2[np]  = b_ih2[n] + b_hh2[n];
    }
    if (np < 15) {
        const float* src = (np < 5) ? (W_mix + np * 512)
                         : (np < 10) ? (W_mu + (np - 5) * 512)
                                     : (W_var + (np - 10) * 512);
        g_Whead[np * 512 + k] = src[k];
        if (k == 0)
            g_bhead[np] = (np < 5) ? b_mix[np] : (np < 10) ? b_mu[np - 5] : b_var[np - 10];
    }
}

// ---------------- TF32 GEMM tile with fused epilogues -----------------------
// C[4096, N] = A[4096, K] @ Bw[N, K]^T (NT, both K-contiguous)
// modes: 0=idea(tanh), 1=base1(+bias), 2=LSTM1 fused, 3=LSTM2 fused (K=1024)
#define BM 128
#define BN 128
#define BK 32
#define STG 3
#define ASTR 36
#define STAGE_FLOATS (2 * 128 * ASTR)   // 9216 floats per stage (A+B)

__device__ void gemm_tile(int mode, int pp,
                          const float* __restrict__ xA,
                          const float* __restrict__ xB,
                          const float* __restrict__ xbias,
                          int m0, int n0, float* smem)
{
    const int tid  = threadIdx.x;
    const int lane = tid & 31;
    const int warp = tid >> 5;
    const int wm   = warp & 3;     // 4 warps along M (32 rows each)
    const int wn   = warp >> 2;    // 4 warps along N (32 cols each)

    const float* A0; const float* A1 = nullptr; const float* Bw;
    int K;
    if      (mode == 0) { A0 = xA;           Bw = xB;       K = 512;  }
    else if (mode == 1) { A0 = g_idea;       Bw = g_Wih1r;  K = 512;  }
    else if (mode == 2) { A0 = g_h1[pp];     Bw = g_Whh1r;  K = 512;  }
    else                { A0 = g_h1[pp ^ 1]; A1 = g_h2[pp]; Bw = g_W2r; K = 1024; }
    const int KT = K / BK;

    float acc[2][4][4];
    #pragma unroll
    for (int a = 0; a < 2; ++a)
        #pragma unroll
        for (int b = 0; b < 4; ++b)
            #pragma unroll
            for (int c = 0; c < 4; ++c) acc[a][b][c] = 0.f;

    auto load_tile = [&](int buf, int kt) {
        const int k0 = kt * BK;
        const float* Asrc = A0; int kk = k0;
        if (A1 != nullptr && k0 >= 512) { Asrc = A1; kk = k0 - 512; }
        float* as = smem + buf * STAGE_FLOATS;
        float* bs = as + 128 * ASTR;
        #pragma unroll
        for (int i = 0; i < 2; ++i) {
            int cid = tid + NTHR * i;
            int row = cid >> 3;
            int c4  = (cid & 7) << 2;
            cp16(&as[row * ASTR + c4], &Asrc[(size_t)(m0 + row) * 512 + kk + c4]);
        }
        #pragma unroll
        for (int i = 0; i < 2; ++i) {
            int cid = tid + NTHR * i;
            int row = cid >> 3;
            int c4  = (cid & 7) << 2;
            cp16(&bs[row * ASTR + c4], &Bw[(size_t)(n0 + row) * K + k0 + c4]);
        }
    };

    auto compute = [&](int buf) {
        const float* as = smem + buf * STAGE_FLOATS;
        const float* bs = as + 128 * ASTR;
        #pragma unroll
        for (int ks = 0; ks < 4; ++ks) {
            const int kb = ks * 8 + (lane & 3);
            uint32_t af[2][4];
            #pragma unroll
            for (int tm = 0; tm < 2; ++tm) {
                int r = wm * 32 + tm * 16 + (lane >> 2);
                af[tm][0] = __float_as_uint(as[r * ASTR + kb]);
                af[tm][1] = __float_as_uint(as[(r + 8) * ASTR + kb]);
                af[tm][2] = __float_as_uint(as[r * ASTR + kb + 4]);
                af[tm][3] = __float_as_uint(as[(r + 8) * ASTR + kb + 4]);
            }
            uint32_t bf[4][2];
            #pragma unroll
            for (int tn = 0; tn < 4; ++tn) {
                int r = wn * 32 + tn * 8 + (lane >> 2);
                bf[tn][0] = __float_as_uint(bs[r * ASTR + kb]);
                bf[tn][1] = __float_as_uint(bs[r * ASTR + kb + 4]);
            }
            #pragma unroll
            for (int tm = 0; tm < 2; ++tm)
                #pragma unroll
                for (int tn = 0; tn < 4; ++tn)
                    asm volatile(
                        "mma.sync.aligned.m16n8k8.row.col.f32.tf32.tf32.f32 "
                        "{%0,%1,%2,%3},{%4,%5,%6,%7},{%8,%9},{%0,%1,%2,%3};\n"
                        : "+f"(acc[tm][tn][0]), "+f"(acc[tm][tn][1]),
                          "+f"(acc[tm][tn][2]), "+f"(acc[tm][tn][3])
                        : "r"(af[tm][0]), "r"(af[tm][1]), "r"(af[tm][2]), "r"(af[tm][3]),
                          "r"(bf[tn][0]), "r"(bf[tn][1]));
        }
    };

    // 3-stage cp.async pipeline
    #pragma unroll
    for (int s = 0; s < STG - 1; ++s) {
        load_tile(s, s);
        asm volatile("cp.async.commit_group;\n");
    }
    asm volatile("cp.async.wait_group %0;\n" :: "n"(STG - 2));
    __syncthreads();

    for (int kt = 0; kt < KT; ++kt) {
        int nk = kt + STG - 1;
        if (nk < KT) load_tile(nk % STG, nk);
        asm volatile("cp.async.commit_group;\n");
        compute(kt % STG);
        asm volatile("cp.async.wait_group %0;\n" :: "n"(STG - 2));
        __syncthreads();
    }
    asm volatile("cp.async.wait_group 0;\n");

    // ---- epilogue: park accumulators in smem, then fused math -------------
    float* gs = smem;   // 128 x 132 f32 tile reusing pipeline smem
    #pragma unroll
    for (int tm = 0; tm < 2; ++tm) {
        #pragma unroll
        for (int tn = 0; tn < 4; ++tn) {
            int r = wm * 32 + tm * 16 + (lane >> 2);
            int c = wn * 32 + tn * 8 + ((lane & 3) << 1);
            gs[r * 132 + c]           = acc[tm][tn][0];
            gs[r * 132 + c + 1]       = acc[tm][tn][1];
            gs[(r + 8) * 132 + c]     = acc[tm][tn][2];
            gs[(r + 8) * 132 + c + 1] = acc[tm][tn][3];
        }
    }
    __syncthreads();

    #pragma unroll 4
    for (int i = 0; i < 8; ++i) {
        int t   = i * NTHR + tid;
        int row = t >> 5, q = t & 31;
        int b   = m0 + row;
        int np  = n0 + (q << 2);
        float4 v = *(float4*)&gs[row * 132 + (q << 2)];

        if (mode == 0) {
            float4 bb = *(const float4*)&xbias[np];
            float4 o;
            o.x = tf32r(tanh_f(v.x + bb.x));
            o.y = tf32r(tanh_f(v.y + bb.y));
            o.z = tf32r(tanh_f(v.z + bb.z));
            o.w = tf32r(tanh_f(v.w + bb.w));
            *(float4*)&g_idea[(size_t)b * 512 + np] = o;
        } else if (mode == 1) {
            float4 bb = *(const float4*)&g_bias1[np];
            v.x += bb.x; v.y += bb.y; v.z += bb.z; v.w += bb.w;
            *(float4*)&g_base1[(size_t)b * 2048 + np] = v;
        } else {
            float gi, gf, gg, go;
            float* cbuf; float* hout;
            if (mode == 2) {
                float4 bb = *(const float4*)&g_base1[(size_t)b * 2048 + np];
                float4 wp = *(const float4*)&g_wprev1[np];
                float ang = g_angles[b];
                gi = v.x + bb.x + ang * wp.x;
                gf = v.y + bb.y + ang * wp.y;
                gg = v.z + bb.z + ang * wp.z;
                go = v.w + bb.w + ang * wp.w;
                cbuf = g_c1; hout = g_h1[pp ^ 1];
            } else {
                float4 bb = *(const float4*)&g_bias2[np];
                gi = v.x + bb.x; gf = v.y + bb.y;
                gg = v.z + bb.z; go = v.w + bb.w;
                cbuf = g_c2; hout = g_h2[pp ^ 1];
            }
            int u = np >> 2;                       // global unit index
            size_t ci = (size_t)b * 512 + u;
            float cold = cbuf[ci];
            float si = sigmoid_f(gi);
            float sf = sigmoid_f(gf);
            float so = sigmoid_f(go);
            float cn = sf * cold + si * tanh_f(gg);
            cbuf[ci] = cn;
            hout[ci] = tf32r(so * tanh_f(cn));
        }
    }
    __syncthreads();
}

__global__ void __launch_bounds__(NTHR, 1)
gemm_kernel(int mode, int pp,
            const float* __restrict__ xA,
            const float* __restrict__ xB,
            const float* __restrict__ xbias)
{
    extern __shared__ float smem[];
    gemm_tile(mode, pp, xA, xB, xbias, blockIdx.y * BM, blockIdx.x * BN, smem);
}

// ---------------- MDN head: one warp per batch row --------------------------
__device__ __forceinline__ void head_row(const float* __restrict__ eps,
                                         float* __restrict__ out,
                                         int s, int hp, int gw, int lane)
{
    const float* h = &g_h2[hp][(size_t)gw * RNN];

    float accv[15];
    #pragma unroll
    for (int j = 0; j < 15; ++j) accv[j] = 0.f;
    #pragma unroll
    for (int i = 0; i < 16; ++i) {
        float hv = h[lane + 32 * i];
        #pragma unroll
        for (int j = 0; j < 15; ++j)
            accv[j] += hv * g_Whead[j * 512 + 32 * i + lane];
    }
    #pragma unroll
    for (int j = 0; j < 15; ++j) {
        #pragma unroll
        for (int off = 16; off; off >>= 1)
            accv[j] += __shfl_xor_sync(0xffffffffu, accv[j], off);
    }
    if (lane == 0) {
        float lmax = -1e30f;
        #pragma unroll
        for (int j = 0; j < 5; ++j) {
            accv[j] += g_bhead[j];
            lmax = fmaxf(lmax, accv[j]);
        }
        float e[5], esum = 0.f;
        #pragma unroll
        for (int j = 0; j < 5; ++j) { e[j] = __expf(accv[j] - lmax); esum += e[j]; }
        float inv = 1.f / esum;
        float mu = 0.f, sg = 0.f;
        #pragma unroll
        for (int j = 0; j < 5; ++j) {
            float rho = e[j] * inv;
            mu += rho * (accv[5 + j] + g_bhead[5 + j]);
            sg += rho * __expf(accv[10 + j] + g_bhead[10 + j]);   // t = 0
        }
        float a = tanh_f(mu + sg * eps[(size_t)s * BATCH + gw]);
        g_angles[gw] = a;
        ((float2*)out)[(size_t)gw * SEG + s] = make_float2(a, 0.f);
    }
}

// ---------------- persistent kernel: all 512 steps ---------------------------
__global__ void __launch_bounds__(NTHR, 1)
persist_kernel(const float* __restrict__ eps, float* __restrict__ out)
{
    extern __shared__ float smem[];
    __shared__ int s_tile;
    int epoch = 0;
    const int lane = threadIdx.x & 31;
    const int wg   = blockIdx.x * 16 + (threadIdx.x >> 5);   // global warp id

    for (int s = 0; s < SEG; ++s) {
        int pp = s & 1;

        // phase A: LSTM1 (dynamic 128x128 tiles, 512 total)
        for (;;) {
            __syncthreads();
            if (threadIdx.x == 0) s_tile = atomicAdd(&g_ctrs[2 * s], 1);
            __syncthreads();
            int t = s_tile;
            if (t >= 512) break;
            gemm_tile(2, pp, nullptr, nullptr, nullptr,
                      (t >> 4) * BM, (t & 15) * BN, smem);
        }
        gsync(epoch);

        // phase B: LSTM2 (K=1024)
        for (;;) {
            __syncthreads();
            if (threadIdx.x == 0) s_tile = atomicAdd(&g_ctrs[2 * s + 1], 1);
            __syncthreads();
            int t = s_tile;
            if (t >= 512) break;
            gemm_tile(3, pp, nullptr, nullptr, nullptr,
                      (t >> 4) * BM, (t & 15) * BN, smem);
        }
        gsync(epoch);

        // phase C: MDN heads (one warp per batch row)
        for (int row = wg; row < BATCH; row += NCTA * 16)
            head_row(eps, out, s, pp ^ 1, row, lane);
        gsync(epoch);
    }
}

// ---------------- launch ----------------------------------------------------
extern "C" void kernel_launch(void* const* d_in, const int* in_sizes, int n_in,
                              void* d_out, int out_size)
{
    const float* latent   = (const float*)d_in[0];
    const float* W_unpack = (const float*)d_in[1];
    const float* b_unpack = (const float*)d_in[2];
    const float* W_ih1    = (const float*)d_in[3];
    const float* W_hh1    = (const float*)d_in[4];
    const float* b_ih1    = (const float*)d_in[5];
    const float* b_hh1    = (const float*)d_in[6];
    const float* W_ih2    = (const float*)d_in[7];
    const float* W_hh2    = (const float*)d_in[8];
    const float* b_ih2    = (const float*)d_in[9];
    const float* b_hh2    = (const float*)d_in[10];
    const float* W_mu     = (const float*)d_in[11];
    const float* b_mu     = (const float*)d_in[12];
    const float* W_var    = (const float*)d_in[13];
    const float* b_var    = (const float*)d_in[14];
    const float* W_mix    = (const float*)d_in[15];
    const float* b_mix    = (const float*)d_in[16];
    const float* eps      = (const float*)d_in[17];
    float* out = (float*)d_out;

    const size_t shmem = (size_t)STG * STAGE_FLOATS * sizeof(float);   // 110592 B
    cudaFuncSetAttribute(gemm_kernel, cudaFuncAttributeMaxDynamicSharedMemorySize,
                         (int)shmem);
    cudaFuncSetAttribute(persist_kernel, cudaFuncAttributeMaxDynamicSharedMemorySize,
                         (int)shmem);

    zero_kernel<<<(BATCH * RNN + 255) / 256, 256>>>();
    reorder_kernel<<<GATES, 512>>>(W_ih1, W_hh1, b_ih1, b_hh1,
                                   W_ih2, W_hh2, b_ih2, b_hh2,
                                   W_mu, b_mu, W_var, b_var, W_mix, b_mix);

    // one-time: idea = tanh(latent @ W_unpack^T + b_unpack)
    gemm_kernel<<<dim3(CODE / BN, BATCH / BM), NTHR, shmem>>>(0, 0, latent, W_unpack, b_unpack);
    // one-time: base1 = idea @ W_ih1'[:, :512]^T + b_ih1 + b_hh1 (interleaved)
    gemm_kernel<<<dim3(GATES / BN, BATCH / BM), NTHR, shmem>>>(1, 0, nullptr, nullptr, nullptr);

    // all 512 steps in ONE persistent kernel (5 graph nodes total)
    persist_kernel<<<NCTA, NTHR, shmem>>>(eps, out);
}

// round 14
// speedup vs baseline: 1.2917x; 1.1190x over previous
#include <cuda_runtime.h>
#include <cstdint>

// ---------------------------------------------------------------------------
// GeneratorNetwork: 512-step 2-layer LSTM (B=4096, H=512) + MDN head.
//   * idea = tanh(latent @ W_unpack^T + b) precomputed once.
//   * base1 = idea @ W_ih1[:, :512]^T + b_ih1 + b_hh1 precomputed once.
//   * ONE persistent kernel runs all 512 steps (software grid barrier).
//   * TF32 mma.sync GEMMs with fused LSTM cell epilogues; gate weights
//     pre-interleaved (n' = unit*4 + gate); h1/h2 ping-pong.
//   * R13: mainloop operands stored as contiguous bank-swizzled 16KB tiles
//     (128x32 f32, word = r*32 + (c ^ ((r&7)<<2))); each k-tile fetched by
//     TWO cp.async.bulk instructions + mbarrier instead of 2048 cp.async.
//   * R14: fix head_row weight index -- tiled h2 word (lane^sw) holds
//     element col `lane`, so the weight index must be `lane` (was lane^sw,
//     corrupting 7/8 of batch rows -> rel_err 0.141).
// ---------------------------------------------------------------------------

#define BATCH 4096
#define RNN   512
#define CODE  512
#define GATES 2048
#define SEG   512
#define NCTA  148
#define NTHR  512

#define TILE_FLOATS 4096           // 128 x 32 tile
#define TILE_BYTES  16384

// ---------------- device state (no cudaMalloc allowed) --------------------
__device__ __align__(256) float g_idea [BATCH * CODE];
__device__ __align__(256) float g_base1[BATCH * GATES];
__device__ __align__(256) float g_h1[2][BATCH * RNN];      // TILED layout
__device__ __align__(256) float g_c1   [BATCH * RNN];
__device__ __align__(256) float g_h2[2][BATCH * RNN];      // TILED layout
__device__ __align__(256) float g_c2   [BATCH * RNN];
__device__ __align__(256) float g_angles[BATCH];
__device__ __align__(256) float g_Wih1r[GATES * RNN];      // linear (mode-1 only)
__device__ __align__(256) float g_Whh1t[GATES * RNN];      // TILED [16nt][16kt]
__device__ __align__(256) float g_W2t  [GATES * 1024];     // TILED [16nt][32kt]
__device__ __align__(256) float g_wprev1[GATES];
__device__ __align__(256) float g_bias1[GATES];
__device__ __align__(256) float g_bias2[GATES];
__device__ __align__(256) float g_Whead[15 * RNN];
__device__ __align__(256) float g_bhead[16];
__device__ int g_bar;
__device__ int g_ctrs[2 * SEG];

// ---------------- helpers --------------------------------------------------
__device__ __forceinline__ float tf32r(float x) {
    uint32_t u;
    asm("cvt.rna.tf32.f32 %0, %1;\n" : "=r"(u) : "f"(x));
    return __uint_as_float(u);
}

__device__ __forceinline__ void cp16(float* dst, const float* src) {
    uint32_t d = (uint32_t)__cvta_generic_to_shared(dst);
    asm volatile("cp.async.cg.shared.global [%0], [%1], 16;\n" :: "r"(d), "l"(src));
}

__device__ __forceinline__ void bulk_cp(uint32_t dst_smem, const float* src,
                                        uint32_t mbar) {
    asm volatile(
        "cp.async.bulk.shared::cta.global.mbarrier::complete_tx::bytes "
        "[%0], [%1], %2, [%3];\n"
        :: "r"(dst_smem), "l"(src), "r"((uint32_t)TILE_BYTES), "r"(mbar)
        : "memory");
}

__device__ __forceinline__ void mbar_init(uint32_t mbar, uint32_t count) {
    asm volatile("mbarrier.init.shared::cta.b64 [%0], %1;\n"
                 :: "r"(mbar), "r"(count) : "memory");
}

__device__ __forceinline__ void mbar_expect_tx(uint32_t mbar, uint32_t bytes) {
    asm volatile("mbarrier.arrive.expect_tx.shared::cta.b64 _, [%0], %1;\n"
                 :: "r"(mbar), "r"(bytes) : "memory");
}

__device__ __forceinline__ void mbar_wait(uint32_t mbar, int phase) {
    asm volatile(
        "{\n\t"
        ".reg .pred P;\n"
        "WAITLP_%=:\n\t"
        "mbarrier.try_wait.parity.acquire.cta.shared::cta.b64 P, [%0], %1, 0x989680;\n\t"
        "@P bra.uni WAITDN_%=;\n\t"
        "bra.uni WAITLP_%=;\n"
        "WAITDN_%=:\n\t"
        "}"
        :: "r"(mbar), "r"((uint32_t)phase) : "memory");
}

__device__ __forceinline__ float sigmoid_f(float x) {
    return 1.0f / (1.0f + __expf(-x));
}
__device__ __forceinline__ float tanh_f(float x) {
    x = fminf(fmaxf(x, -15.f), 15.f);
    float e = __expf(2.f * x);
    return (e - 1.f) / (e + 1.f);
}

// software grid barrier (all 148 CTAs co-resident: 1 CTA/SM by smem usage)
__device__ __forceinline__ void gsync(int& epoch) {
    __syncthreads();
    if (threadIdx.x == 0) {
        int target = (++epoch) * (int)gridDim.x;
        __threadfence();
        atomicAdd(&g_bar, 1);
        int v;
        do {
            asm volatile("ld.acquire.gpu.global.s32 %0, [%1];"
                         : "=r"(v) : "l"(&g_bar));
        } while (v < target);
    }
    __syncthreads();
}

// tiled-swizzled index: tile word for (row r in 0..127, col c in 0..31)
__device__ __forceinline__ int tsw(int r, int c) {
    return r * 32 + (c ^ ((r & 7) << 2));
}

// ---------------- init + reorder -------------------------------------------
__global__ void zero_kernel() {
    size_t i = (size_t)blockIdx.x * blockDim.x + threadIdx.x;
    if (i < (size_t)BATCH * RNN) {
        g_h1[0][i] = 0.f; g_h2[0][i] = 0.f;
        g_c1[i]    = 0.f; g_c2[i]    = 0.f;
    }
    if (i < BATCH) g_angles[i] = 0.f;
    if (i < 2 * SEG) g_ctrs[i] = 0;
    if (i == 0) g_bar = 0;
}

__global__ void reorder_kernel(
    const float* __restrict__ W_ih1, const float* __restrict__ W_hh1,
    const float* __restrict__ b_ih1, const float* __restrict__ b_hh1,
    const float* __restrict__ W_ih2, const float* __restrict__ W_hh2,
    const float* __restrict__ b_ih2, const float* __restrict__ b_hh2,
    const float* __restrict__ W_mu,  const float* __restrict__ b_mu,
    const float* __restrict__ W_var, const float* __restrict__ b_var,
    const float* __restrict__ W_mix, const float* __restrict__ b_mix)
{
    int np = blockIdx.x;          // interleaved gate index 0..2047
    int k  = threadIdx.x;         // 0..511
    int gate = np & 3, unit = np >> 2;
    int n = gate * 512 + unit;    // original row in the 4*RNN weight matrices

    int nt = np >> 7, r = np & 127;

    g_Wih1r[np * 512 + k] = tf32r(W_ih1[n * 514 + k]);   // W_ih1 is [2048, 514]

    // tiled + swizzled weight stores
    g_Whh1t[((size_t)nt * 16 + (k >> 5)) * TILE_FLOATS + tsw(r, k & 31)]
        = tf32r(W_hh1[n * 512 + k]);
    g_W2t[((size_t)nt * 32 + (k >> 5)) * TILE_FLOATS + tsw(r, k & 31)]
        = tf32r(W_ih2[n * 512 + k]);
    g_W2t[((size_t)nt * 32 + 16 + (k >> 5)) * TILE_FLOATS + tsw(r, k & 31)]
        = tf32r(W_hh2[n * 512 + k]);

    if (k == 0) {
        g_wprev1[np] = W_ih1[n * 514 + 512];
        g_bias1[np]  = b_ih1[n] + b_hh1[n];
        g_bias2[np]  = b_ih2[n] + b_hh2[n];
    }
    if (np < 15) {
        const float* src = (np < 5) ? (W_mix + np * 512)
                         : (np < 10) ? (W_mu + (np - 5) * 512)
                                     : (W_var + (np - 10) * 512);
        g_Whead[np * 512 + k] = src[k];
        if (k == 0)
            g_bhead[np] = (np < 5) ? b_mix[np] : (np < 10) ? b_mu[np - 5] : b_var[np - 10];
    }
}

// ======================= one-time legacy GEMM (modes 0/1) ===================
#define BM 128
#define BN 128
#define BK 32
#define STG 3
#define ASTR 36
#define L_STAGE_FLOATS (2 * 128 * ASTR)

__global__ void __launch_bounds__(NTHR, 1)
gemm_kernel(int mode,
            const float* __restrict__ xA,
            const float* __restrict__ xB,
            const float* __restrict__ xbias)
{
    extern __shared__ float smem[];
    const int tid  = threadIdx.x;
    const int lane = tid & 31;
    const int warp = tid >> 5;
    const int wm   = warp & 3;
    const int wn   = warp >> 2;
    const int m0   = blockIdx.y * BM;
    const int n0   = blockIdx.x * BN;

    const float* A0 = (mode == 0) ? xA : g_idea;
    const float* Bw = (mode == 0) ? xB : g_Wih1r;
    const int K = 512, KT = 16;

    float acc[2][4][4];
    #pragma unroll
    for (int a = 0; a < 2; ++a)
        #pragma unroll
        for (int b = 0; b < 4; ++b)
            #pragma unroll
            for (int c = 0; c < 4; ++c) acc[a][b][c] = 0.f;

    auto load_tile = [&](int buf, int kt) {
        const int k0 = kt * BK;
        float* as = smem + buf * L_STAGE_FLOATS;
        float* bs = as + 128 * ASTR;
        #pragma unroll
        for (int i = 0; i < 2; ++i) {
            int cid = tid + NTHR * i;
            int row = cid >> 3;
            int c4  = (cid & 7) << 2;
            cp16(&as[row * ASTR + c4], &A0[(size_t)(m0 + row) * 512 + k0 + c4]);
        }
        #pragma unroll
        for (int i = 0; i < 2; ++i) {
            int cid = tid + NTHR * i;
            int row = cid >> 3;
            int c4  = (cid & 7) << 2;
            cp16(&bs[row * ASTR + c4], &Bw[(size_t)(n0 + row) * K + k0 + c4]);
        }
    };

    auto compute = [&](int buf) {
        const float* as = smem + buf * L_STAGE_FLOATS;
        const float* bs = as + 128 * ASTR;
        #pragma unroll
        for (int ks = 0; ks < 4; ++ks) {
            const int kb = ks * 8 + (lane & 3);
            uint32_t af[2][4];
            #pragma unroll
            for (int tm = 0; tm < 2; ++tm) {
                int r = wm * 32 + tm * 16 + (lane >> 2);
                af[tm][0] = __float_as_uint(as[r * ASTR + kb]);
                af[tm][1] = __float_as_uint(as[(r + 8) * ASTR + kb]);
                af[tm][2] = __float_as_uint(as[r * ASTR + kb + 4]);
                af[tm][3] = __float_as_uint(as[(r + 8) * ASTR + kb + 4]);
            }
            uint32_t bf[4][2];
            #pragma unroll
            for (int tn = 0; tn < 4; ++tn) {
                int r = wn * 32 + tn * 8 + (lane >> 2);
                bf[tn][0] = __float_as_uint(bs[r * ASTR + kb]);
                bf[tn][1] = __float_as_uint(bs[r * ASTR + kb + 4]);
            }
            #pragma unroll
            for (int tm = 0; tm < 2; ++tm)
                #pragma unroll
                for (int tn = 0; tn < 4; ++tn)
                    asm volatile(
                        "mma.sync.aligned.m16n8k8.row.col.f32.tf32.tf32.f32 "
                        "{%0,%1,%2,%3},{%4,%5,%6,%7},{%8,%9},{%0,%1,%2,%3};\n"
                        : "+f"(acc[tm][tn][0]), "+f"(acc[tm][tn][1]),
                          "+f"(acc[tm][tn][2]), "+f"(acc[tm][tn][3])
                        : "r"(af[tm][0]), "r"(af[tm][1]), "r"(af[tm][2]), "r"(af[tm][3]),
                          "r"(bf[tn][0]), "r"(bf[tn][1]));
        }
    };

    #pragma unroll
    for (int s = 0; s < STG - 1; ++s) {
        load_tile(s, s);
        asm volatile("cp.async.commit_group;\n");
    }
    asm volatile("cp.async.wait_group %0;\n" :: "n"(STG - 2));
    __syncthreads();

    for (int kt = 0; kt < KT; ++kt) {
        int nk = kt + STG - 1;
        if (nk < KT) load_tile(nk % STG, nk);
        asm volatile("cp.async.commit_group;\n");
        compute(kt % STG);
        asm volatile("cp.async.wait_group %0;\n" :: "n"(STG - 2));
        __syncthreads();
    }
    asm volatile("cp.async.wait_group 0;\n");

    float* gs = smem;
    #pragma unroll
    for (int tm = 0; tm < 2; ++tm) {
        #pragma unroll
        for (int tn = 0; tn < 4; ++tn) {
            int r = wm * 32 + tm * 16 + (lane >> 2);
            int c = wn * 32 + tn * 8 + ((lane & 3) << 1);
            gs[r * 132 + c]           = acc[tm][tn][0];
            gs[r * 132 + c + 1]       = acc[tm][tn][1];
            gs[(r + 8) * 132 + c]     = acc[tm][tn][2];
            gs[(r + 8) * 132 + c + 1] = acc[tm][tn][3];
        }
    }
    __syncthreads();

    #pragma unroll 4
    for (int i = 0; i < 8; ++i) {
        int t   = i * NTHR + tid;
        int row = t >> 5, q = t & 31;
        int b   = m0 + row;
        int np  = n0 + (q << 2);
        float4 v = *(float4*)&gs[row * 132 + (q << 2)];
        if (mode == 0) {
            float4 bb = *(const float4*)&xbias[np];
            float4 o;
            o.x = tf32r(tanh_f(v.x + bb.x));
            o.y = tf32r(tanh_f(v.y + bb.y));
            o.z = tf32r(tanh_f(v.z + bb.z));
            o.w = tf32r(tanh_f(v.w + bb.w));
            *(float4*)&g_idea[(size_t)b * 512 + np] = o;
        } else {
            float4 bb = *(const float4*)&g_bias1[np];
            v.x += bb.x; v.y += bb.y; v.z += bb.z; v.w += bb.w;
            *(float4*)&g_base1[(size_t)b * 2048 + np] = v;
        }
    }
}

// ======================= persistent mainloop GEMM (modes 2/3) ===============
// smem: 3 stages x (A 16KB + B 16KB) = 96KB, mbarriers at byte 98304.
#define P_STAGE_FLOATS (2 * TILE_FLOATS)      // 8192 floats per stage
#define MBAR_OFF 98304

__device__ void gemm_tile_bulk(int mode, int pp, int m0, int n0,
                               float* smem, uint32_t smem_u32, int* ph)
{
    const int tid  = threadIdx.x;
    const int lane = tid & 31;
    const int warp = tid >> 5;
    const int wm   = warp & 3;     // 4 warps along M (32 rows each)
    const int wn   = warp >> 2;    // 4 warps along N (32 cols each)
    const int q    = lane >> 2;    // fragment row-in-group
    const int tt   = lane & 3;     // fragment col-in-group
    const int KT   = (mode == 2) ? 16 : 32;
    const int mt   = m0 >> 7;
    const int nt   = n0 >> 7;

    // per-ktile source tiles (contiguous 16KB, pre-swizzled)
    const float* h1a = g_h1[(mode == 2) ? pp : (pp ^ 1)];
    const float* h2a = g_h2[pp];
    const float* Bwt = (mode == 2) ? (g_Whh1t + (size_t)nt * 16 * TILE_FLOATS)
                                   : (g_W2t   + (size_t)nt * 32 * TILE_FLOATS);

    auto a_src = [&](int kt) -> const float* {
        if (mode == 2) return h1a + ((size_t)mt * 16 + kt) * TILE_FLOATS;
        return (kt < 16) ? h1a + ((size_t)mt * 16 + kt) * TILE_FLOATS
                         : h2a + ((size_t)mt * 16 + (kt - 16)) * TILE_FLOATS;
    };

    auto issue = [&](int buf, int kt) {
        uint32_t mb = smem_u32 + MBAR_OFF + buf * 16;
        mbar_expect_tx(mb, 2 * TILE_BYTES);
        bulk_cp(smem_u32 + buf * (2 * TILE_BYTES), a_src(kt), mb);
        bulk_cp(smem_u32 + buf * (2 * TILE_BYTES) + TILE_BYTES,
                Bwt + (size_t)kt * TILE_FLOATS, mb);
    };

    float acc[2][4][4];
    #pragma unroll
    for (int a = 0; a < 2; ++a)
        #pragma unroll
        for (int b = 0; b < 4; ++b)
            #pragma unroll
            for (int c = 0; c < 4; ++c) acc[a][b][c] = 0.f;

    auto compute = [&](int buf) {
        const float* as = smem + buf * P_STAGE_FLOATS;
        const float* bs = as + TILE_FLOATS;
        #pragma unroll
        for (int ks = 0; ks < 4; ++ks) {
            const int sk = (ks * 8 + tt) ^ (q << 2);   // swizzled col
            uint32_t af[2][4];
            #pragma unroll
            for (int tm = 0; tm < 2; ++tm) {
                int r = wm * 32 + tm * 16 + q;
                af[tm][0] = __float_as_uint(as[r * 32 + sk]);
                af[tm][1] = __float_as_uint(as[(r + 8) * 32 + sk]);
                af[tm][2] = __float_as_uint(as[r * 32 + (sk ^ 4)]);
                af[tm][3] = __float_as_uint(as[(r + 8) * 32 + (sk ^ 4)]);
            }
            uint32_t bf[4][2];
            #pragma unroll
            for (int tn = 0; tn < 4; ++tn) {
                int r = wn * 32 + tn * 8 + q;
                bf[tn][0] = __float_as_uint(bs[r * 32 + sk]);
                bf[tn][1] = __float_as_uint(bs[r * 32 + (sk ^ 4)]);
            }
            #pragma unroll
            for (int tm = 0; tm < 2; ++tm)
                #pragma unroll
                for (int tn = 0; tn < 4; ++tn)
                    asm volatile(
                        "mma.sync.aligned.m16n8k8.row.col.f32.tf32.tf32.f32 "
                        "{%0,%1,%2,%3},{%4,%5,%6,%7},{%8,%9},{%0,%1,%2,%3};\n"
                        : "+f"(acc[tm][tn][0]), "+f"(acc[tm][tn][1]),
                          "+f"(acc[tm][tn][2]), "+f"(acc[tm][tn][3])
                        : "r"(af[tm][0]), "r"(af[tm][1]), "r"(af[tm][2]), "r"(af[tm][3]),
                          "r"(bf[tn][0]), "r"(bf[tn][1]));
        }
    };

    // 3-stage bulk-copy pipeline
    if (tid == 0) { issue(0, 0); issue(1, 1); }

    for (int kt = 0; kt < KT; ++kt) {
        int nk = kt + 2;
        if (nk < KT && tid == 0) issue(nk % 3, nk);
        int buf = kt % 3;
        mbar_wait(smem_u32 + MBAR_OFF + buf * 16, ph[buf]);
        ph[buf] ^= 1;
        compute(buf);
        __syncthreads();             // all reads done before buf is refilled
    }

    // ---- epilogue: park accumulators in smem, then fused LSTM math --------
    float* gs = smem;   // 128 x 132 f32 (67.6KB) over stage data; mbars safe
    #pragma unroll
    for (int tm = 0; tm < 2; ++tm) {
        #pragma unroll
        for (int tn = 0; tn < 4; ++tn) {
            int r = wm * 32 + tm * 16 + q;
            int c = wn * 32 + tn * 8 + (tt << 1);
            gs[r * 132 + c]           = acc[tm][tn][0];
            gs[r * 132 + c + 1]       = acc[tm][tn][1];
            gs[(r + 8) * 132 + c]     = acc[tm][tn][2];
            gs[(r + 8) * 132 + c + 1] = acc[tm][tn][3];
        }
    }
    __syncthreads();

    float* cbuf = (mode == 2) ? g_c1 : g_c2;
    float* hout = (mode == 2) ? g_h1[pp ^ 1] : g_h2[pp ^ 1];

    #pragma unroll 4
    for (int i = 0; i < 8; ++i) {
        int t   = i * NTHR + tid;
        int row = t >> 5, qq = t & 31;
        int b   = m0 + row;
        int np  = n0 + (qq << 2);
        float4 v = *(float4*)&gs[row * 132 + (qq << 2)];

        float gi, gf, gg, go;
        if (mode == 2) {
            float4 bb = *(const float4*)&g_base1[(size_t)b * 2048 + np];
            float4 wp = *(const float4*)&g_wprev1[np];
            float ang = g_angles[b];
            gi = v.x + bb.x + ang * wp.x;
            gf = v.y + bb.y + ang * wp.y;
            gg = v.z + bb.z + ang * wp.z;
            go = v.w + bb.w + ang * wp.w;
        } else {
            float4 bb = *(const float4*)&g_bias2[np];
            gi = v.x + bb.x; gf = v.y + bb.y;
            gg = v.z + bb.z; go = v.w + bb.w;
        }
        int u = np >> 2;
        size_t ci = (size_t)b * 512 + u;
        float cold = cbuf[ci];
        float si = sigmoid_f(gi);
        float sf = sigmoid_f(gf);
        float so = sigmoid_f(go);
        float cn = sf * cold + si * tanh_f(gg);
        cbuf[ci] = cn;
        // tiled + swizzled h store: tile (b>>7, u>>5), word tsw(b&127, u&31)
        hout[((size_t)(b >> 7) * 16 + (u >> 5)) * TILE_FLOATS
             + (b & 127) * 32 + ((u & 31) ^ ((b & 7) << 2))]
            = tf32r(so * tanh_f(cn));
    }
    __syncthreads();
}

// ---------------- MDN head: one warp per batch row (tiled h2 read) ----------
__device__ __forceinline__ void head_row(const float* __restrict__ eps,
                                         float* __restrict__ out,
                                         int s, int hp, int gw, int lane)
{
    const float* ht = g_h2[hp] + (size_t)(gw >> 7) * 16 * TILE_FLOATS;
    const int r  = gw & 127;
    const int rb = r * 32;
    const int sw = (r & 7) << 2;

    float accv[15];
    #pragma unroll
    for (int j = 0; j < 15; ++j) accv[j] = 0.f;
    #pragma unroll
    for (int i = 0; i < 16; ++i) {
        // word (lane ^ sw) holds logical element col `lane` (R14 fix:
        // weight index must be `lane`, NOT lane^sw)
        float hv = ht[i * TILE_FLOATS + rb + (lane ^ sw)];
        #pragma unroll
        for (int j = 0; j < 15; ++j)
            accv[j] += hv * g_Whead[j * 512 + 32 * i + lane];
    }
    #pragma unroll
    for (int j = 0; j < 15; ++j) {
        #pragma unroll
        for (int off = 16; off; off >>= 1)
            accv[j] += __shfl_xor_sync(0xffffffffu, accv[j], off);
    }
    if (lane == 0) {
        float lmax = -1e30f;
        #pragma unroll
        for (int j = 0; j < 5; ++j) {
            accv[j] += g_bhead[j];
            lmax = fmaxf(lmax, accv[j]);
        }
        float e[5], esum = 0.f;
        #pragma unroll
        for (int j = 0; j < 5; ++j) { e[j] = __expf(accv[j] - lmax); esum += e[j]; }
        float inv = 1.f / esum;
        float mu = 0.f, sg = 0.f;
        #pragma unroll
        for (int j = 0; j < 5; ++j) {
            float rho = e[j] * inv;
            mu += rho * (accv[5 + j] + g_bhead[5 + j]);
            sg += rho * __expf(accv[10 + j] + g_bhead[10 + j]);   // t = 0
        }
        float a = tanh_f(mu + sg * eps[(size_t)s * BATCH + gw]);
        g_angles[gw] = a;
        ((float2*)out)[(size_t)gw * SEG + s] = make_float2(a, 0.f);
    }
}

// ---------------- persistent kernel: all 512 steps ---------------------------
__global__ void __launch_bounds__(NTHR, 1)
persist_kernel(const float* __restrict__ eps, float* __restrict__ out)
{
    extern __shared__ float smem[];
    __shared__ int s_tile;
    const uint32_t smem_u32 =
        (uint32_t)__cvta_generic_to_shared(smem);
    int epoch = 0;
    int ph[3] = {0, 0, 0};
    const int lane = threadIdx.x & 31;
    const int wg   = blockIdx.x * 16 + (threadIdx.x >> 5);

    // init stage mbarriers (CTA-local)
    if (threadIdx.x < 3)
        mbar_init(smem_u32 + MBAR_OFF + threadIdx.x * 16, 1);
    __syncthreads();

    for (int s = 0; s < SEG; ++s) {
        int pp = s & 1;

        // phase A: LSTM1 (dynamic 128x128 tiles, 512 total)
        for (;;) {
            __syncthreads();
            if (threadIdx.x == 0) s_tile = atomicAdd(&g_ctrs[2 * s], 1);
            __syncthreads();
            int t = s_tile;
            if (t >= 512) break;
            gemm_tile_bulk(2, pp, (t >> 4) * BM, (t & 15) * BN,
                           smem, smem_u32, ph);
        }
        gsync(epoch);

        // phase B: LSTM2 (K=1024)
        for (;;) {
            __syncthreads();
            if (threadIdx.x == 0) s_tile = atomicAdd(&g_ctrs[2 * s + 1], 1);
            __syncthreads();
            int t = s_tile;
            if (t >= 512) break;
            gemm_tile_bulk(3, pp, (t >> 4) * BM, (t & 15) * BN,
                           smem, smem_u32, ph);
        }
        gsync(epoch);

        // phase C: MDN heads (one warp per batch row)
        for (int row = wg; row < BATCH; row += NCTA * 16)
            head_row(eps, out, s, pp ^ 1, row, lane);
        gsync(epoch);
    }
}

// ---------------- launch ----------------------------------------------------
extern "C" void kernel_launch(void* const* d_in, const int* in_sizes, int n_in,
                              void* d_out, int out_size)
{
    const float* latent   = (const float*)d_in[0];
    const float* W_unpack = (const float*)d_in[1];
    const float* b_unpack = (const float*)d_in[2];
    const float* W_ih1    = (const float*)d_in[3];
    const float* W_hh1    = (const float*)d_in[4];
    const float* b_ih1    = (const float*)d_in[5];
    const float* b_hh1    = (const float*)d_in[6];
    const float* W_ih2    = (const float*)d_in[7];
    const float* W_hh2    = (const float*)d_in[8];
    const float* b_ih2    = (const float*)d_in[9];
    const float* b_hh2    = (const float*)d_in[10];
    const float* W_mu     = (const float*)d_in[11];
    const float* b_mu     = (const float*)d_in[12];
    const float* W_var    = (const float*)d_in[13];
    const float* b_var    = (const float*)d_in[14];
    const float* W_mix    = (const float*)d_in[15];
    const float* b_mix    = (const float*)d_in[16];
    const float* eps      = (const float*)d_in[17];
    float* out = (float*)d_out;

    // 122880 B: > 114KB keeps 1 CTA/SM (grid-barrier safety) for both kernels
    const size_t shmem = 122880;
    cudaFuncSetAttribute(gemm_kernel, cudaFuncAttributeMaxDynamicSharedMemorySize,
                         (int)shmem);
    cudaFuncSetAttribute(persist_kernel, cudaFuncAttributeMaxDynamicSharedMemorySize,
                         (int)shmem);

    zero_kernel<<<(BATCH * RNN + 255) / 256, 256>>>();
    reorder_kernel<<<GATES, 512>>>(W_ih1, W_hh1, b_ih1, b_hh1,
                                   W_ih2, W_hh2, b_ih2, b_hh2,
                                   W_mu, b_mu, W_var, b_var, W_mix, b_mix);

    // one-time: idea = tanh(latent @ W_unpack^T + b_unpack)
    gemm_kernel<<<dim3(CODE / BN, BATCH / BM), NTHR, shmem>>>(0, latent, W_unpack, b_unpack);
    // one-time: base1 = idea @ W_ih1'[:, :512]^T + b_ih1 + b_hh1 (interleaved)
    gemm_kernel<<<dim3(GATES / BN, BATCH / BM), NTHR, shmem>>>(1, nullptr, nullptr, nullptr);

    // all 512 steps in ONE persistent kernel
    persist_kernel<<<NCTA, NTHR, shmem>>>(eps, out);
}

// round 17
// speedup vs baseline: 1.4364x; 1.1121x over previous
#include <cuda_runtime.h>
#include <cstdint>

// ---------------------------------------------------------------------------
// GeneratorNetwork: 512-step 2-layer LSTM (B=4096, H=512) + MDN head.
//   * idea / base1 precomputed once (legacy mma.sync kernels, negligible).
//   * ONE persistent kernel runs all 512 steps (software grid barrier).
//   * Operands as contiguous SW128-swizzled 16KB tiles (word =
//     r*32 + (c ^ ((r&7)<<2))); h tiles produced directly by LSTM epilogue.
//   * R16: tcgen05 unavailable (harness targets sm_103, no 'a' features) --
//     stay on mma.sync. BK 32 -> 64: 64KB stages x3 (192KB smem, sm_103 has
//     227KB), SAME 2 bulk-copy instructions per k-tile (sources contiguous),
//     halving per-tile mbar_wait/__syncthreads/issue overhead. Accumulation
//     order unchanged -> rel_err must reproduce 8.783923e-5 exactly.
//   * Dummy 5th launch makes persist_kernel launch #6 = the one ncu captures.
// ---------------------------------------------------------------------------

#define BATCH 4096
#define RNN   512
#define CODE  512
#define GATES 2048
#define SEG   512
#define NCTA  148
#define NTHR  512

#define TILE_FLOATS 4096           // 128 x 32 f32 tile (128B rows, SW128)
#define TILE_BYTES  16384

// persistent-kernel smem: 3 stages x 64KB (A 32KB + B 32KB), mbars after
#define P_STAGE_FLOATS 16384       // floats per stage
#define FULL_OFF 196608            // 3 x 16B full mbarriers
#define P_SMEM_REQ 197696          // FULL_OFF + 48 + align slack

// ---------------- device state (no cudaMalloc allowed) --------------------
__device__ __align__(256) float g_idea [BATCH * CODE];
__device__ __align__(256) float g_base1[BATCH * GATES];
__device__ __align__(256) float g_h1[2][BATCH * RNN];      // TILED layout
__device__ __align__(256) float g_c1   [BATCH * RNN];
__device__ __align__(256) float g_h2[2][BATCH * RNN];      // TILED layout
__device__ __align__(256) float g_c2   [BATCH * RNN];
__device__ __align__(256) float g_angles[BATCH];
__device__ __align__(256) float g_Wih1r[GATES * RNN];      // linear (mode-1 only)
__device__ __align__(256) float g_Whh1t[GATES * RNN];      // TILED [16nt][16kt]
__device__ __align__(256) float g_W2t  [GATES * 1024];     // TILED [16nt][32kt]
__device__ __align__(256) float g_wprev1[GATES];
__device__ __align__(256) float g_bias1[GATES];
__device__ __align__(256) float g_bias2[GATES];
__device__ __align__(256) float g_Whead[15 * RNN];
__device__ __align__(256) float g_bhead[16];
__device__ int g_bar;
__device__ int g_ctrs[2 * SEG];

// ---------------- helpers --------------------------------------------------
__device__ __forceinline__ float tf32r(float x) {
    uint32_t u;
    asm("cvt.rna.tf32.f32 %0, %1;\n" : "=r"(u) : "f"(x));
    return __uint_as_float(u);
}

__device__ __forceinline__ void cp16(float* dst, const float* src) {
    uint32_t d = (uint32_t)__cvta_generic_to_shared(dst);
    asm volatile("cp.async.cg.shared.global [%0], [%1], 16;\n" :: "r"(d), "l"(src));
}

__device__ __forceinline__ void bulk_cp(uint32_t dst_smem, const float* src,
                                        uint32_t bytes, uint32_t mbar) {
    asm volatile(
        "cp.async.bulk.shared::cta.global.mbarrier::complete_tx::bytes "
        "[%0], [%1], %2, [%3];\n"
        :: "r"(dst_smem), "l"(src), "r"(bytes), "r"(mbar)
        : "memory");
}

__device__ __forceinline__ void mbar_init(uint32_t mbar, uint32_t count) {
    asm volatile("mbarrier.init.shared::cta.b64 [%0], %1;\n"
                 :: "r"(mbar), "r"(count) : "memory");
}

__device__ __forceinline__ void mbar_expect_tx(uint32_t mbar, uint32_t bytes) {
    asm volatile("mbarrier.arrive.expect_tx.shared::cta.b64 _, [%0], %1;\n"
                 :: "r"(mbar), "r"(bytes) : "memory");
}

__device__ __forceinline__ void mbar_wait(uint32_t mbar, int phase) {
    asm volatile(
        "{\n\t"
        ".reg .pred P;\n"
        "WAITLP_%=:\n\t"
        "mbarrier.try_wait.parity.acquire.cta.shared::cta.b64 P, [%0], %1, 0x989680;\n\t"
        "@P bra.uni WAITDN_%=;\n\t"
        "bra.uni WAITLP_%=;\n"
        "WAITDN_%=:\n\t"
        "}"
        :: "r"(mbar), "r"((uint32_t)phase) : "memory");
}

__device__ __forceinline__ float sigmoid_f(float x) {
    return 1.0f / (1.0f + __expf(-x));
}
__device__ __forceinline__ float tanh_f(float x) {
    x = fminf(fmaxf(x, -15.f), 15.f);
    float e = __expf(2.f * x);
    return (e - 1.f) / (e + 1.f);
}

// software grid barrier (148 CTAs co-resident: 1 CTA/SM by smem usage)
__device__ __forceinline__ void gsync(int& epoch) {
    __syncthreads();
    if (threadIdx.x == 0) {
        int target = (++epoch) * (int)gridDim.x;
        __threadfence();
        atomicAdd(&g_bar, 1);
        int v;
        do {
            asm volatile("ld.acquire.gpu.global.s32 %0, [%1];"
                         : "=r"(v) : "l"(&g_bar));
        } while (v < target);
    }
    __syncthreads();
}

// tiled-swizzled index (== SW128 atom swizzle for 128B rows)
__device__ __forceinline__ int tsw(int r, int c) {
    return r * 32 + (c ^ ((r & 7) << 2));
}

// ---------------- init + reorder -------------------------------------------
__global__ void zero_kernel() {
    size_t i = (size_t)blockIdx.x * blockDim.x + threadIdx.x;
    if (i < (size_t)BATCH * RNN) {
        g_h1[0][i] = 0.f; g_h2[0][i] = 0.f;
        g_c1[i]    = 0.f; g_c2[i]    = 0.f;
    }
    if (i < BATCH) g_angles[i] = 0.f;
    if (i < 2 * SEG) g_ctrs[i] = 0;
    if (i == 0) g_bar = 0;
}

__global__ void dummy_kernel() {}   // shifts persist_kernel to launch #6 (ncu -s 5)

__global__ void reorder_kernel(
    const float* __restrict__ W_ih1, const float* __restrict__ W_hh1,
    const float* __restrict__ b_ih1, const float* __restrict__ b_hh1,
    const float* __restrict__ W_ih2, const float* __restrict__ W_hh2,
    const float* __restrict__ b_ih2, const float* __restrict__ b_hh2,
    const float* __restrict__ W_mu,  const float* __restrict__ b_mu,
    const float* __restrict__ W_var, const float* __restrict__ b_var,
    const float* __restrict__ W_mix, const float* __restrict__ b_mix)
{
    int np = blockIdx.x;          // interleaved gate index 0..2047
    int k  = threadIdx.x;         // 0..511
    int gate = np & 3, unit = np >> 2;
    int n = gate * 512 + unit;

    int nt = np >> 7, r = np & 127;

    g_Wih1r[np * 512 + k] = tf32r(W_ih1[n * 514 + k]);   // W_ih1 is [2048, 514]

    g_Whh1t[((size_t)nt * 16 + (k >> 5)) * TILE_FLOATS + tsw(r, k & 31)]
        = tf32r(W_hh1[n * 512 + k]);
    g_W2t[((size_t)nt * 32 + (k >> 5)) * TILE_FLOATS + tsw(r, k & 31)]
        = tf32r(W_ih2[n * 512 + k]);
    g_W2t[((size_t)nt * 32 + 16 + (k >> 5)) * TILE_FLOATS + tsw(r, k & 31)]
        = tf32r(W_hh2[n * 512 + k]);

    if (k == 0) {
        g_wprev1[np] = W_ih1[n * 514 + 512];
        g_bias1[np]  = b_ih1[n] + b_hh1[n];
        g_bias2[np]  = b_ih2[n] + b_hh2[n];
    }
    if (np < 15) {
        const float* src = (np < 5) ? (W_mix + np * 512)
                         : (np < 10) ? (W_mu + (np - 5) * 512)
                                     : (W_var + (np - 10) * 512);
        g_Whead[np * 512 + k] = src[k];
        if (k == 0)
            g_bhead[np] = (np < 5) ? b_mix[np] : (np < 10) ? b_mu[np - 5] : b_var[np - 10];
    }
}

// ======================= one-time legacy GEMM (modes 0/1) ===================
#define BM 128
#define BN 128
#define BK 32
#define STG 3
#define ASTR 36
#define L_STAGE_FLOATS (2 * 128 * ASTR)

__global__ void __launch_bounds__(NTHR, 1)
gemm_kernel(int mode,
            const float* __restrict__ xA,
            const float* __restrict__ xB,
            const float* __restrict__ xbias)
{
    extern __shared__ float smem[];
    const int tid  = threadIdx.x;
    const int lane = tid & 31;
    const int warp = tid >> 5;
    const int wm   = warp & 3;
    const int wn   = warp >> 2;
    const int m0   = blockIdx.y * BM;
    const int n0   = blockIdx.x * BN;

    const float* A0 = (mode == 0) ? xA : g_idea;
    const float* Bw = (mode == 0) ? xB : g_Wih1r;
    const int K = 512, KT = 16;

    float acc[2][4][4];
    #pragma unroll
    for (int a = 0; a < 2; ++a)
        #pragma unroll
        for (int b = 0; b < 4; ++b)
            #pragma unroll
            for (int c = 0; c < 4; ++c) acc[a][b][c] = 0.f;

    auto load_tile = [&](int buf, int kt) {
        const int k0 = kt * BK;
        float* as = smem + buf * L_STAGE_FLOATS;
        float* bs = as + 128 * ASTR;
        #pragma unroll
        for (int i = 0; i < 2; ++i) {
            int cid = tid + NTHR * i;
            int row = cid >> 3;
            int c4  = (cid & 7) << 2;
            cp16(&as[row * ASTR + c4], &A0[(size_t)(m0 + row) * 512 + k0 + c4]);
        }
        #pragma unroll
        for (int i = 0; i < 2; ++i) {
            int cid = tid + NTHR * i;
            int row = cid >> 3;
            int c4  = (cid & 7) << 2;
            cp16(&bs[row * ASTR + c4], &Bw[(size_t)(n0 + row) * K + k0 + c4]);
        }
    };

    auto compute = [&](int buf) {
        const float* as = smem + buf * L_STAGE_FLOATS;
        const float* bs = as + 128 * ASTR;
        #pragma unroll
        for (int ks = 0; ks < 4; ++ks) {
            const int kb = ks * 8 + (lane & 3);
            uint32_t af[2][4];
            #pragma unroll
            for (int tm = 0; tm < 2; ++tm) {
                int r = wm * 32 + tm * 16 + (lane >> 2);
                af[tm][0] = __float_as_uint(as[r * ASTR + kb]);
                af[tm][1] = __float_as_uint(as[(r + 8) * ASTR + kb]);
                af[tm][2] = __float_as_uint(as[r * ASTR + kb + 4]);
                af[tm][3] = __float_as_uint(as[(r + 8) * ASTR + kb + 4]);
            }
            uint32_t bf[4][2];
            #pragma unroll
            for (int tn = 0; tn < 4; ++tn) {
                int r = wn * 32 + tn * 8 + (lane >> 2);
                bf[tn][0] = __float_as_uint(bs[r * ASTR + kb]);
                bf[tn][1] = __float_as_uint(bs[r * ASTR + kb + 4]);
            }
            #pragma unroll
            for (int tm = 0; tm < 2; ++tm)
                #pragma unroll
                for (int tn = 0; tn < 4; ++tn)
                    asm volatile(
                        "mma.sync.aligned.m16n8k8.row.col.f32.tf32.tf32.f32 "
                        "{%0,%1,%2,%3},{%4,%5,%6,%7},{%8,%9},{%0,%1,%2,%3};\n"
                        : "+f"(acc[tm][tn][0]), "+f"(acc[tm][tn][1]),
                          "+f"(acc[tm][tn][2]), "+f"(acc[tm][tn][3])
                        : "r"(af[tm][0]), "r"(af[tm][1]), "r"(af[tm][2]), "r"(af[tm][3]),
                          "r"(bf[tn][0]), "r"(bf[tn][1]));
        }
    };

    #pragma unroll
    for (int s = 0; s < STG - 1; ++s) {
        load_tile(s, s);
        asm volatile("cp.async.commit_group;\n");
    }
    asm volatile("cp.async.wait_group %0;\n" :: "n"(STG - 2));
    __syncthreads();

    for (int kt = 0; kt < KT; ++kt) {
        int nk = kt + STG - 1;
        if (nk < KT) load_tile(nk % STG, nk);
        asm volatile("cp.async.commit_group;\n");
        compute(kt % STG);
        asm volatile("cp.async.wait_group %0;\n" :: "n"(STG - 2));
        __syncthreads();
    }
    asm volatile("cp.async.wait_group 0;\n");

    float* gs = smem;
    #pragma unroll
    for (int tm = 0; tm < 2; ++tm) {
        #pragma unroll
        for (int tn = 0; tn < 4; ++tn) {
            int r = wm * 32 + tm * 16 + (lane >> 2);
            int c = wn * 32 + tn * 8 + ((lane & 3) << 1);
            gs[r * 132 + c]           = acc[tm][tn][0];
            gs[r * 132 + c + 1]       = acc[tm][tn][1];
            gs[(r + 8) * 132 + c]     = acc[tm][tn][2];
            gs[(r + 8) * 132 + c + 1] = acc[tm][tn][3];
        }
    }
    __syncthreads();

    #pragma unroll 4
    for (int i = 0; i < 8; ++i) {
        int t   = i * NTHR + tid;
        int row = t >> 5, q = t & 31;
        int b   = m0 + row;
        int np  = n0 + (q << 2);
        float4 v = *(float4*)&gs[row * 132 + (q << 2)];
        if (mode == 0) {
            float4 bb = *(const float4*)&xbias[np];
            float4 o;
            o.x = tf32r(tanh_f(v.x + bb.x));
            o.y = tf32r(tanh_f(v.y + bb.y));
            o.z = tf32r(tanh_f(v.z + bb.z));
            o.w = tf32r(tanh_f(v.w + bb.w));
            *(float4*)&g_idea[(size_t)b * 512 + np] = o;
        } else {
            float4 bb = *(const float4*)&g_bias1[np];
            v.x += bb.x; v.y += bb.y; v.z += bb.z; v.w += bb.w;
            *(float4*)&g_base1[(size_t)b * 2048 + np] = v;
        }
    }
}

// ======================= persistent mainloop GEMM (modes 2/3) ===============
// BK=64 super-k-tiles: 64KB stages (A 2x16KB + B 2x16KB), 3 stages = 192KB.
// Sources are contiguous 32KB blocks -> still only 2 bulk copies per stage.

__device__ void gemm_tile_bulk(int mode, int pp, int m0, int n0,
                               float* sf, uint32_t s0, int* phf)
{
    const int tid  = threadIdx.x;
    const int lane = tid & 31;
    const int warp = tid >> 5;
    const int wm   = warp & 3;     // 4 warps along M (32 rows each)
    const int wn   = warp >> 2;    // 4 warps along N (32 cols each)
    const int q    = lane >> 2;
    const int tt   = lane & 3;
    const int SKT  = (mode == 2) ? 8 : 16;    // 64-wide super k-tiles
    const int mt   = m0 >> 7;
    const int nt   = n0 >> 7;

    const float* h1a = g_h1[(mode == 2) ? pp : (pp ^ 1)];
    const float* h2a = g_h2[pp];
    const float* Bwt = (mode == 2) ? (g_Whh1t + (size_t)nt * 16 * TILE_FLOATS)
                                   : (g_W2t   + (size_t)nt * 32 * TILE_FLOATS);

    auto a_src = [&](int skt) -> const float* {   // 32KB contiguous (2 tiles)
        int kt = 2 * skt;
        if (mode == 2) return h1a + ((size_t)mt * 16 + kt) * TILE_FLOATS;
        return (kt < 16) ? h1a + ((size_t)mt * 16 + kt) * TILE_FLOATS
                         : h2a + ((size_t)mt * 16 + (kt - 16)) * TILE_FLOATS;
    };

    auto issue = [&](int buf, int skt) {
        uint32_t mb = s0 + FULL_OFF + buf * 16;
        mbar_expect_tx(mb, 4 * TILE_BYTES);
        bulk_cp(s0 + buf * (4 * TILE_BYTES), a_src(skt), 2 * TILE_BYTES, mb);
        bulk_cp(s0 + buf * (4 * TILE_BYTES) + 2 * TILE_BYTES,
                Bwt + (size_t)(2 * skt) * TILE_FLOATS, 2 * TILE_BYTES, mb);
    };

    float acc[2][4][4];
    #pragma unroll
    for (int a = 0; a < 2; ++a)
        #pragma unroll
        for (int b = 0; b < 4; ++b)
            #pragma unroll
            for (int c = 0; c < 4; ++c) acc[a][b][c] = 0.f;

    auto compute = [&](int buf) {
        #pragma unroll
        for (int ks = 0; ks < 8; ++ks) {
            const int j  = ks >> 2;               // sub-tile 0/1
            const float* as = sf + buf * P_STAGE_FLOATS + j * TILE_FLOATS;
            const float* bs = sf + buf * P_STAGE_FLOATS + 2 * TILE_FLOATS
                                 + j * TILE_FLOATS;
            const int sk = (((ks & 3) * 8) + tt) ^ (q << 2);   // swizzled col
            uint32_t af[2][4];
            #pragma unroll
            for (int tm = 0; tm < 2; ++tm) {
                int r = wm * 32 + tm * 16 + q;
                af[tm][0] = __float_as_uint(as[r * 32 + sk]);
                af[tm][1] = __float_as_uint(as[(r + 8) * 32 + sk]);
                af[tm][2] = __float_as_uint(as[r * 32 + (sk ^ 4)]);
                af[tm][3] = __float_as_uint(as[(r + 8) * 32 + (sk ^ 4)]);
            }
            uint32_t bf[4][2];
            #pragma unroll
            for (int tn = 0; tn < 4; ++tn) {
                int r = wn * 32 + tn * 8 + q;
                bf[tn][0] = __float_as_uint(bs[r * 32 + sk]);
                bf[tn][1] = __float_as_uint(bs[r * 32 + (sk ^ 4)]);
            }
            #pragma unroll
            for (int tm = 0; tm < 2; ++tm)
                #pragma unroll
                for (int tn = 0; tn < 4; ++tn)
                    asm volatile(
                        "mma.sync.aligned.m16n8k8.row.col.f32.tf32.tf32.f32 "
                        "{%0,%1,%2,%3},{%4,%5,%6,%7},{%8,%9},{%0,%1,%2,%3};\n"
                        : "+f"(acc[tm][tn][0]), "+f"(acc[tm][tn][1]),
                          "+f"(acc[tm][tn][2]), "+f"(acc[tm][tn][3])
                        : "r"(af[tm][0]), "r"(af[tm][1]), "r"(af[tm][2]), "r"(af[tm][3]),
                          "r"(bf[tn][0]), "r"(bf[tn][1]));
        }
    };

    // 3-stage bulk pipeline over super k-tiles
    if (tid == 0) { issue(0, 0); issue(1, 1); }

    for (int skt = 0; skt < SKT; ++skt) {
        int nk = skt + 2;
        // buffer (skt-1)%3 was fully read by end of previous iteration (sync)
        if (nk < SKT && tid == 0) issue(nk % 3, nk);
        int buf = skt % 3;
        mbar_wait(s0 + FULL_OFF + 16 * buf, phf[buf]);
        phf[buf] ^= 1;
        compute(buf);
        __syncthreads();
    }

    // ---- epilogue: park accumulators in smem, then fused LSTM math --------
    float* gs = sf;   // 128 x 132 f32 (67.6KB) over stage data; mbars safe
    #pragma unroll
    for (int tm = 0; tm < 2; ++tm) {
        #pragma unroll
        for (int tn = 0; tn < 4; ++tn) {
            int r = wm * 32 + tm * 16 + q;
            int c = wn * 32 + tn * 8 + (tt << 1);
            gs[r * 132 + c]           = acc[tm][tn][0];
            gs[r * 132 + c + 1]       = acc[tm][tn][1];
            gs[(r + 8) * 132 + c]     = acc[tm][tn][2];
            gs[(r + 8) * 132 + c + 1] = acc[tm][tn][3];
        }
    }
    __syncthreads();

    float* cbuf = (mode == 2) ? g_c1 : g_c2;
    float* hout = (mode == 2) ? g_h1[pp ^ 1] : g_h2[pp ^ 1];

    #pragma unroll 4
    for (int i = 0; i < 8; ++i) {
        int t   = i * NTHR + tid;
        int row = t >> 5, qq = t & 31;
        int b   = m0 + row;
        int np  = n0 + (qq << 2);
        float4 v = *(float4*)&gs[row * 132 + (qq << 2)];

        float gi, gf, gg, go;
        if (mode == 2) {
            float4 bb = *(const float4*)&g_base1[(size_t)b * 2048 + np];
            float4 wp = *(const float4*)&g_wprev1[np];
            float ang = g_angles[b];
            gi = v.x + bb.x + ang * wp.x;
            gf = v.y + bb.y + ang * wp.y;
            gg = v.z + bb.z + ang * wp.z;
            go = v.w + bb.w + ang * wp.w;
        } else {
            float4 bb = *(const float4*)&g_bias2[np];
            gi = v.x + bb.x; gf = v.y + bb.y;
            gg = v.z + bb.z; go = v.w + bb.w;
        }
        int u = np >> 2;
        size_t ci = (size_t)b * 512 + u;
        float cold = cbuf[ci];
        float si = sigmoid_f(gi);
        float sf_ = sigmoid_f(gf);
        float so = sigmoid_f(go);
        float cn = sf_ * cold + si * tanh_f(gg);
        cbuf[ci] = cn;
        // tiled + swizzled h store: tile (b>>7, u>>5), word tsw(b&127, u&31)
        hout[((size_t)(b >> 7) * 16 + (u >> 5)) * TILE_FLOATS
             + (b & 127) * 32 + ((u & 31) ^ ((b & 7) << 2))]
            = tf32r(so * tanh_f(cn));
    }
    __syncthreads();
}

// ---------------- MDN head: one warp per batch row (tiled h2 read) ----------
__device__ __forceinline__ void head_row(const float* __restrict__ eps,
                                         float* __restrict__ out,
                                         int s, int hp, int gw, int lane)
{
    const float* ht = g_h2[hp] + (size_t)(gw >> 7) * 16 * TILE_FLOATS;
    const int r  = gw & 127;
    const int rb = r * 32;
    const int sw = (r & 7) << 2;

    float accv[15];
    #pragma unroll
    for (int j = 0; j < 15; ++j) accv[j] = 0.f;
    #pragma unroll
    for (int i = 0; i < 16; ++i) {
        // word (lane ^ sw) holds logical element col `lane`
        float hv = ht[i * TILE_FLOATS + rb + (lane ^ sw)];
        #pragma unroll
        for (int j = 0; j < 15; ++j)
            accv[j] += hv * g_Whead[j * 512 + 32 * i + lane];
    }
    #pragma unroll
    for (int j = 0; j < 15; ++j) {
        #pragma unroll
        for (int off = 16; off; off >>= 1)
            accv[j] += __shfl_xor_sync(0xffffffffu, accv[j], off);
    }
    if (lane == 0) {
        float lmax = -1e30f;
        #pragma unroll
        for (int j = 0; j < 5; ++j) {
            accv[j] += g_bhead[j];
            lmax = fmaxf(lmax, accv[j]);
        }
        float e[5], esum = 0.f;
        #pragma unroll
        for (int j = 0; j < 5; ++j) { e[j] = __expf(accv[j] - lmax); esum += e[j]; }
        float inv = 1.f / esum;
        float mu = 0.f, sg = 0.f;
        #pragma unroll
        for (int j = 0; j < 5; ++j) {
            float rho = e[j] * inv;
            mu += rho * (accv[5 + j] + g_bhead[5 + j]);
            sg += rho * __expf(accv[10 + j] + g_bhead[10 + j]);   // t = 0
        }
        float a = tanh_f(mu + sg * eps[(size_t)s * BATCH + gw]);
        g_angles[gw] = a;
        ((float2*)out)[(size_t)gw * SEG + s] = make_float2(a, 0.f);
    }
}

// ---------------- persistent kernel: all 512 steps ---------------------------
__global__ void __launch_bounds__(NTHR, 1)
persist_kernel(const float* __restrict__ eps, float* __restrict__ out)
{
    extern __shared__ float smem[];
    __shared__ int s_tile;
    uint32_t raw = (uint32_t)__cvta_generic_to_shared(smem);
    uint32_t s0  = (raw + 1023u) & ~1023u;         // 1KB-align for swizzle base
    float* sf = (float*)((char*)smem + (s0 - raw));

    const int tid  = threadIdx.x;
    const int lane = tid & 31;
    const int wg   = blockIdx.x * 16 + (tid >> 5);

    if (tid == 0) {
        #pragma unroll
        for (int i = 0; i < 3; ++i)
            mbar_init(s0 + FULL_OFF + 16 * i, 1);
    }
    __syncthreads();

    int epoch = 0;
    int phf[3] = {0, 0, 0};

    for (int s = 0; s < SEG; ++s) {
        int pp = s & 1;

        // phase A: LSTM1 (dynamic 128x128 tiles, 512 total)
        for (;;) {
            __syncthreads();
            if (tid == 0) s_tile = atomicAdd(&g_ctrs[2 * s], 1);
            __syncthreads();
            int t = s_tile;
            if (t >= 512) break;
            gemm_tile_bulk(2, pp, (t >> 4) * BM, (t & 15) * BN, sf, s0, phf);
        }
        gsync(epoch);

        // phase B: LSTM2 (K=1024)
        for (;;) {
            __syncthreads();
            if (tid == 0) s_tile = atomicAdd(&g_ctrs[2 * s + 1], 1);
            __syncthreads();
            int t = s_tile;
            if (t >= 512) break;
            gemm_tile_bulk(3, pp, (t >> 4) * BM, (t & 15) * BN, sf, s0, phf);
        }
        gsync(epoch);

        // phase C: MDN heads (one warp per batch row)
        for (int row = wg; row < BATCH; row += NCTA * 16)
            head_row(eps, out, s, pp ^ 1, row, lane);
        gsync(epoch);
    }
}

// ---------------- launch ----------------------------------------------------
extern "C" void kernel_launch(void* const* d_in, const int* in_sizes, int n_in,
                              void* d_out, int out_size)
{
    const float* latent   = (const float*)d_in[0];
    const float* W_unpack = (const float*)d_in[1];
    const float* b_unpack = (const float*)d_in[2];
    const float* W_ih1    = (const float*)d_in[3];
    const float* W_hh1    = (const float*)d_in[4];
    const float* b_ih1    = (const float*)d_in[5];
    const float* b_hh1    = (const float*)d_in[6];
    const float* W_ih2    = (const float*)d_in[7];
    const float* W_hh2    = (const float*)d_in[8];
    const float* b_ih2    = (const float*)d_in[9];
    const float* b_hh2    = (const float*)d_in[10];
    const float* W_mu     = (const float*)d_in[11];
    const float* b_mu     = (const float*)d_in[12];
    const float* W_var    = (const float*)d_in[13];
    const float* b_var    = (const float*)d_in[14];
    const float* W_mix    = (const float*)d_in[15];
    const float* b_mix    = (const float*)d_in[16];
    const float* eps      = (const float*)d_in[17];
    float* out = (float*)d_out;

    const size_t l_shmem = 122880;
    cudaFuncSetAttribute(gemm_kernel, cudaFuncAttributeMaxDynamicSharedMemorySize,
                         (int)l_shmem);
    cudaFuncSetAttribute(persist_kernel, cudaFuncAttributeMaxDynamicSharedMemorySize,
                         P_SMEM_REQ);

    zero_kernel<<<(BATCH * RNN + 255) / 256, 256>>>();                      // 1
    reorder_kernel<<<GATES, 512>>>(W_ih1, W_hh1, b_ih1, b_hh1,              // 2
                                   W_ih2, W_hh2, b_ih2, b_hh2,
                                   W_mu, b_mu, W_var, b_var, W_mix, b_mix);

    // one-time: idea = tanh(latent @ W_unpack^T + b_unpack)
    gemm_kernel<<<dim3(CODE / BN, BATCH / BM), NTHR, l_shmem>>>(            // 3
        0, latent, W_unpack, b_unpack);
    // one-time: base1 = idea @ W_ih1'[:, :512]^T + biases (interleaved)
    gemm_kernel<<<dim3(GATES / BN, BATCH / BM), NTHR, l_shmem>>>(           // 4
        1, nullptr, nullptr, nullptr);

    dummy_kernel<<<1, 32>>>();                                              // 5

    // all 512 steps in ONE persistent kernel (launch #6 -> ncu -s 5 target)
    persist_kernel<<<NCTA, NTHR, P_SMEM_REQ>>>(eps, out);                   // 6
}